// round 8
// baseline (speedup 1.0000x reference)
#include <cuda_runtime.h>

typedef unsigned long long u64;

// ---------------------------------------------------------------------------
// Packed f32x2 helpers (Blackwell packed fp32 math)
// ---------------------------------------------------------------------------
__device__ __forceinline__ u64 pack2(float a, float b) {
    u64 r;
    asm("mov.b64 %0, {%1, %2};" : "=l"(r) : "f"(a), "f"(b));
    return r;
}
__device__ __forceinline__ void unpack2(u64 v, float& a, float& b) {
    asm("mov.b64 {%0, %1}, %2;" : "=f"(a), "=f"(b) : "l"(v));
}
__device__ __forceinline__ u64 fma2(u64 a, u64 b, u64 c) {
    u64 r;
    asm("fma.rn.f32x2 %0, %1, %2, %3;" : "=l"(r) : "l"(a), "l"(b), "l"(c));
    return r;
}
__device__ __forceinline__ u64 mul2(u64 a, u64 b) {
    u64 r;
    asm("mul.rn.f32x2 %0, %1, %2;" : "=l"(r) : "l"(a), "l"(b));
    return r;
}

// ---------------------------------------------------------------------------
// Per-step combined rotation constants (Bloch form of Rz(th1)*Ry(th0)),
// duplicated into both f32x2 lanes. Layout per step t (8 u64):
//   A=cc*cb, nSC=-sc, B=cc*sb, D=sc*cb, CC=cc, E=sc*sb, nSB=-sb, CB=cb
// ---------------------------------------------------------------------------
__device__   u64 g_consts_dev[32 * 8];
__constant__ u64 c_consts[32 * 8];

__global__ void prep_consts_kernel(const float* __restrict__ theta) {
    int t = threadIdx.x;
    if (t < 32) {
        float th0 = theta[2 * t + 0];
        float th1 = theta[2 * t + 1];
        float sb = sinf(th0), cb = cosf(th0);  // Ry full angle (Bloch sphere)
        float sc = sinf(th1), cc = cosf(th1);  // Rz full angle (Bloch sphere)
        float v[8] = { cc * cb, -sc, cc * sb, sc * cb,
                       cc, sc * sb, -sb, cb };
#pragma unroll
        for (int k = 0; k < 8; k++) {
            u64 p;
            asm("mov.b64 %0, {%1, %1};" : "=l"(p) : "f"(v[k]));
            g_consts_dev[t * 8 + k] = p;
        }
    }
}

// ---------------------------------------------------------------------------
// Main kernel. Block of 256 threads owns 512 contiguous elements, processed
// in TWO PHASES of 4 float4-chunks each (steps 0-15, then 16-31) so the smem
// tile is only 32KB -> 6 CTAs/SM resident (launch_bounds caps regs).
// Swizzle slot = 4e + ((c + (e>>1)) & 3): conflict-free for both the
// coalesced STS.128 and the per-element strided LDS.128.
// Each thread evolves TWO elements (f32x2 lanes) on the Bloch sphere:
//   r <- Rz(th1)*Ry(th0)*Rx(x_t)*r,  out = r.z*w + b.
// ---------------------------------------------------------------------------
__global__ void __launch_bounds__(256, 6) qsim_kernel(
    const float4* __restrict__ xg,
    const float* __restrict__ w,
    const float* __restrict__ b,
    float* __restrict__ out)
{
    extern __shared__ float4 s_x[];   // 512 elements * 4 float4 = 32KB per phase

    int tid = threadIdx.x;
    size_t blockElem = (size_t)blockIdx.x * 512;
    const float4* gbase = xg + blockElem * 8;

    int e0 = tid;          // lane .x element (local)
    int e1 = tid + 256;    // lane .y element (local)
    int sw0 = e0 >> 1;     // swizzle seed for e0
    int sw1 = e1 >> 1;

    // Bloch vector of |0> for both elements
    u64 rx = pack2(0.0f, 0.0f);
    u64 ry = rx;
    u64 rz = pack2(1.0f, 1.0f);

#pragma unroll
    for (int p = 0; p < 2; p++) {
        if (p) __syncthreads();   // previous phase's reads complete

        // Stage this phase's 4 chunks of every element: 8 x (LDG.128 + STS.128)
#pragma unroll
        for (int k = 0; k < 8; k++) {
            int idx = tid + k * 256;          // float4 index within 32KB half
            int e = idx >> 2;                 // local element
            int c = idx & 3;                  // chunk within phase
            float4 v = __ldcs(gbase + (size_t)e * 8 + p * 4 + c);
            s_x[(e << 2) + ((c + (e >> 1)) & 3)] = v;
        }
        __syncthreads();

#pragma unroll
        for (int c = 0; c < 4; c++) {
            float4 a0 = s_x[(e0 << 2) + ((c + sw0) & 3)];   // LDS.128
            float4 a1 = s_x[(e1 << 2) + ((c + sw1) & 3)];
            float xa0[4] = { a0.x, a0.y, a0.z, a0.w };
            float xa1[4] = { a1.x, a1.y, a1.z, a1.w };

#pragma unroll
            for (int j = 0; j < 4; j++) {
                int t = (p * 4 + c) * 4 + j;

                float s0, c0, s1, c1;
                __sincosf(xa0[j], &s0, &c0);               // 2x MUFU
                __sincosf(xa1[j], &s1, &c1);               // 2x MUFU

                u64 sx  = pack2(s0, s1);
                u64 cx  = pack2(c0, c1);
                u64 nsx = pack2(-s0, -s1);

                const u64* cs = &c_consts[t * 8];          // const bank, uniform
                u64 A   = cs[0];
                u64 nSC = cs[1];
                u64 Bc  = cs[2];
                u64 D   = cs[3];
                u64 CC  = cs[4];
                u64 E   = cs[5];
                u64 nSB = cs[6];
                u64 CB  = cs[7];

                // Rx(x_t): rotate (y,z); x unchanged
                u64 y1 = fma2(cx, ry, mul2(nsx, rz));      // cx*ry - sx*rz
                u64 z1 = fma2(sx, ry, mul2(cx, rz));       // sx*ry + cx*rz

                // Rz(th1)*Ry(th0) applied to (rx, y1, z1):
                u64 x2 = fma2(Bc, z1, fma2(nSC, y1, mul2(A, rx)));
                u64 y2 = fma2(E,  z1, fma2(CC,  y1, mul2(D, rx)));
                u64 z2 = fma2(nSB, rx, mul2(CB, z1));

                rx = x2; ry = y2; rz = z2;
            }
        }
    }

    float W  = w[0];
    float Bb = b[0];
    float z_0, z_1;
    unpack2(rz, z_0, z_1);
    out[blockElem + e0] = fmaf(z_0, W, Bb);                // coalesced stores
    out[blockElem + e1] = fmaf(z_1, W, Bb);
}

extern "C" void kernel_launch(void* const* d_in, const int* in_sizes, int n_in,
                              void* d_out, int out_size)
{
    const float* x     = (const float*)d_in[0];   // [B, 32]
    const float* theta = (const float*)d_in[1];   // [32, 2]
    const float* w     = (const float*)d_in[2];   // [1, 1]
    const float* b     = (const float*)d_in[3];   // [1]
    float* out = (float*)d_out;                   // [B]

    int B = in_sizes[0] / 32;

    prep_consts_kernel<<<1, 32>>>(theta);

    // Stage -> constant bank (device-to-device memcpy node, graph-capturable)
    void* staging_ptr = nullptr;
    cudaGetSymbolAddress(&staging_ptr, g_consts_dev);
    cudaMemcpyToSymbolAsync(c_consts, staging_ptr, sizeof(u64) * 32 * 8, 0,
                            cudaMemcpyDeviceToDevice, 0);

    const int SMEM = 512 * 4 * sizeof(float4);    // 32KB dynamic smem
    cudaFuncSetAttribute(qsim_kernel, cudaFuncAttributeMaxDynamicSharedMemorySize, SMEM);

    qsim_kernel<<<B / 512, 256, SMEM>>>((const float4*)x, w, b, out);
}

// round 9
// speedup vs baseline: 1.0154x; 1.0154x over previous
#include <cuda_runtime.h>

typedef unsigned long long u64;

// ---------------------------------------------------------------------------
// Packed f32x2 helpers (Blackwell packed fp32 math)
// ---------------------------------------------------------------------------
__device__ __forceinline__ u64 pack2(float a, float b) {
    u64 r;
    asm("mov.b64 %0, {%1, %2};" : "=l"(r) : "f"(a), "f"(b));
    return r;
}
__device__ __forceinline__ void unpack2(u64 v, float& a, float& b) {
    asm("mov.b64 {%0, %1}, %2;" : "=f"(a), "=f"(b) : "l"(v));
}
__device__ __forceinline__ u64 fma2(u64 a, u64 b, u64 c) {
    u64 r;
    asm("fma.rn.f32x2 %0, %1, %2, %3;" : "=l"(r) : "l"(a), "l"(b), "l"(c));
    return r;
}
__device__ __forceinline__ u64 mul2(u64 a, u64 b) {
    u64 r;
    asm("mul.rn.f32x2 %0, %1, %2;" : "=l"(r) : "l"(a), "l"(b));
    return r;
}

// ---------------------------------------------------------------------------
// Per-step combined rotation constants (Bloch form of Rz(th1)*Ry(th0)),
// duplicated into both f32x2 lanes. Layout per step t (8 u64):
//   A=cc*cb, nSC=-sc, B=cc*sb, D=sc*cb, CC=cc, E=sc*sb, nSB=-sb, CB=cb
// Staged in global by the prep kernel; each block copies them into smem and
// reads them per step as LDS.128 broadcasts (uniform address, conflict-free).
// This removes the LDC constant-port bottleneck (LDC->LDC floor = 8 cyc/SMSP).
// ---------------------------------------------------------------------------
__device__ u64 g_consts_dev[32 * 8];

__global__ void prep_consts_kernel(const float* __restrict__ theta) {
    int t = threadIdx.x;
    if (t < 32) {
        float th0 = theta[2 * t + 0];
        float th1 = theta[2 * t + 1];
        float sb = sinf(th0), cb = cosf(th0);  // Ry full angle (Bloch sphere)
        float sc = sinf(th1), cc = cosf(th1);  // Rz full angle (Bloch sphere)
        float v[8] = { cc * cb, -sc, cc * sb, sc * cb,
                       cc, sc * sb, -sb, cb };
#pragma unroll
        for (int k = 0; k < 8; k++) {
            u64 p;
            asm("mov.b64 %0, {%1, %1};" : "=l"(p) : "f"(v[k]));
            g_consts_dev[t * 8 + k] = p;
        }
    }
}

// ---------------------------------------------------------------------------
// Main kernel (single phase, like the 35.3us version). Block of 256 threads
// owns 512 contiguous elements.
// Phase 1: coalesced LDG.128 of the block's contiguous 64KB x-region into
//          smem with XOR-quad swizzle (slot = (c+e)&7) so both the coalesced
//          store and the strided per-element read are LDS.128 conflict-free.
//          All 16 LDGs issue up front (MLP=16) to overlap DRAM with compute.
// Phase 2: each thread evolves TWO elements (packed f32x2 lanes) through
//          r <- Rz(th1)*Ry(th0)*Rx(x_t)*r on the Bloch sphere; out = r.z*w+b.
// ---------------------------------------------------------------------------
__global__ void __launch_bounds__(256) qsim_kernel(
    const float4* __restrict__ xg,
    const float* __restrict__ w,
    const float* __restrict__ b,
    float* __restrict__ out)
{
    extern __shared__ float4 s_x[];   // 512 elements * 8 float4 = 64KB
    __shared__ u64 s_c[32 * 8];       // 2KB step constants

    int tid = threadIdx.x;
    size_t blockElem = (size_t)blockIdx.x * 512;
    const float4* gbase = xg + blockElem * 8;

    // Stage step constants: one LDG.64 per thread (256 = 32 steps * 8)
    s_c[tid] = g_consts_dev[tid];

    // Coalesced streaming load -> swizzled smem store
#pragma unroll
    for (int k = 0; k < 16; k++) {
        int idx = tid + k * 256;            // linear float4 index in block tile
        float4 v = __ldcs(gbase + idx);     // lanes consecutive: nL=4 per warp
        int e = idx >> 3;                   // local element
        int c = idx & 7;                    // chunk within window
        s_x[(e << 3) + ((c + e) & 7)] = v;  // XOR-quad swizzle
    }
    __syncthreads();

    int e0 = tid;          // lane .x element (local)
    int e1 = tid + 256;    // lane .y element (local)

    // Bloch vector of |0> for both elements
    u64 rx = pack2(0.0f, 0.0f);
    u64 ry = rx;
    u64 rz = pack2(1.0f, 1.0f);

#pragma unroll
    for (int c = 0; c < 8; c++) {
        float4 a0 = s_x[(e0 << 3) + ((c + e0) & 7)];   // LDS.128, conflict-free
        float4 a1 = s_x[(e1 << 3) + ((c + e1) & 7)];
        float xa0[4] = { a0.x, a0.y, a0.z, a0.w };
        float xa1[4] = { a1.x, a1.y, a1.z, a1.w };

#pragma unroll
        for (int j = 0; j < 4; j++) {
            int t = c * 4 + j;

            float s0, c0, s1, c1;
            __sincosf(xa0[j], &s0, &c0);               // 2x MUFU
            __sincosf(xa1[j], &s1, &c1);               // 2x MUFU

            u64 sx  = pack2(s0, s1);
            u64 cx  = pack2(c0, c1);
            u64 nsx = pack2(-s0, -s1);

            // Constants via LDS.128 broadcast (compile-time offsets)
            const u64* cs = &s_c[t * 8];
            ulonglong2 q0 = *reinterpret_cast<const ulonglong2*>(cs + 0); // A, nSC
            ulonglong2 q1 = *reinterpret_cast<const ulonglong2*>(cs + 2); // B, D
            ulonglong2 q2 = *reinterpret_cast<const ulonglong2*>(cs + 4); // CC, E
            ulonglong2 q3 = *reinterpret_cast<const ulonglong2*>(cs + 6); // nSB, CB
            u64 A   = q0.x, nSC = q0.y;
            u64 Bc  = q1.x, D   = q1.y;
            u64 CC  = q2.x, E   = q2.y;
            u64 nSB = q3.x, CB  = q3.y;

            // Rx(x_t): rotate (y,z); x unchanged
            u64 y1 = fma2(cx, ry, mul2(nsx, rz));      // cx*ry - sx*rz
            u64 z1 = fma2(sx, ry, mul2(cx, rz));       // sx*ry + cx*rz

            // Rz(th1)*Ry(th0) applied to (rx, y1, z1):
            u64 x2 = fma2(Bc, z1, fma2(nSC, y1, mul2(A, rx)));
            u64 y2 = fma2(E,  z1, fma2(CC,  y1, mul2(D, rx)));
            u64 z2 = fma2(nSB, rx, mul2(CB, z1));

            rx = x2; ry = y2; rz = z2;
        }
    }

    float W  = w[0];
    float Bb = b[0];
    float z_0, z_1;
    unpack2(rz, z_0, z_1);
    out[blockElem + e0] = fmaf(z_0, W, Bb);            // coalesced stores
    out[blockElem + e1] = fmaf(z_1, W, Bb);
}

extern "C" void kernel_launch(void* const* d_in, const int* in_sizes, int n_in,
                              void* d_out, int out_size)
{
    const float* x     = (const float*)d_in[0];   // [B, 32]
    const float* theta = (const float*)d_in[1];   // [32, 2]
    const float* w     = (const float*)d_in[2];   // [1, 1]
    const float* b     = (const float*)d_in[3];   // [1]
    float* out = (float*)d_out;                   // [B]

    int B = in_sizes[0] / 32;

    prep_consts_kernel<<<1, 32>>>(theta);

    const int SMEM = 512 * 8 * sizeof(float4);    // 64KB dynamic smem
    cudaFuncSetAttribute(qsim_kernel, cudaFuncAttributeMaxDynamicSharedMemorySize, SMEM);

    qsim_kernel<<<B / 512, 256, SMEM>>>((const float4*)x, w, b, out);
}

// round 12
// speedup vs baseline: 1.2572x; 1.2382x over previous
#include <cuda_runtime.h>

typedef unsigned long long u64;

// ---------------------------------------------------------------------------
// Packed f32x2 helpers (Blackwell packed fp32 math)
// ---------------------------------------------------------------------------
__device__ __forceinline__ u64 pack2(float a, float b) {
    u64 r;
    asm("mov.b64 %0, {%1, %2};" : "=l"(r) : "f"(a), "f"(b));
    return r;
}
__device__ __forceinline__ void unpack2(u64 v, float& a, float& b) {
    asm("mov.b64 {%0, %1}, %2;" : "=f"(a), "=f"(b) : "l"(v));
}
__device__ __forceinline__ u64 fma2(u64 a, u64 b, u64 c) {
    u64 r;
    asm("fma.rn.f32x2 %0, %1, %2, %3;" : "=l"(r) : "l"(a), "l"(b), "l"(c));
    return r;
}
__device__ __forceinline__ u64 mul2(u64 a, u64 b) {
    u64 r;
    asm("mul.rn.f32x2 %0, %1, %2;" : "=l"(r) : "l"(a), "l"(b));
    return r;
}

// ---------------------------------------------------------------------------
// Per-step rotation constants for sequential Ry(th0) then Rz(th1) (Bloch,
// full angles), each duplicated into both f32x2 lanes. 3 x ulonglong2 per
// step so the main loop does exactly 3 LDC.128 per step:
//   q0 = (CB, SB), q1 = (CC, SC), q2 = (NSB, NSC)
// ---------------------------------------------------------------------------
__device__   ulonglong2 g_consts_dev[32 * 3];
__constant__ ulonglong2 c_consts[32 * 3];

__device__ __forceinline__ u64 dup2(float a) {
    u64 p;
    asm("mov.b64 %0, {%1, %1};" : "=l"(p) : "f"(a));
    return p;
}

__global__ void prep_consts_kernel(const float* __restrict__ theta) {
    int t = threadIdx.x;
    if (t < 32) {
        float th0 = theta[2 * t + 0];
        float th1 = theta[2 * t + 1];
        float sb = sinf(th0), cb = cosf(th0);  // Ry full angle (Bloch sphere)
        float sc = sinf(th1), cc = cosf(th1);  // Rz full angle (Bloch sphere)
        ulonglong2 q0, q1, q2;
        q0.x = dup2(cb);  q0.y = dup2(sb);
        q1.x = dup2(cc);  q1.y = dup2(sc);
        q2.x = dup2(-sb); q2.y = dup2(-sc);
        g_consts_dev[t * 3 + 0] = q0;
        g_consts_dev[t * 3 + 1] = q1;
        g_consts_dev[t * 3 + 2] = q2;
    }
}

// ---------------------------------------------------------------------------
// Main kernel (single-phase structure of the 35.3us version). Block of 256
// threads owns 512 contiguous elements.
// Phase 1: coalesced LDG.128 of the block's contiguous 64KB x-region into
//          smem with XOR-quad swizzle (slot = (c+e)&7); all 16 LDGs issue up
//          front (MLP=16) so DRAM overlaps the long compute phase.
// Phase 2: each thread evolves TWO elements (packed f32x2 lanes):
//          r <- Rz(th1) * Ry(th0) * Rx(x_t) * r, applied as three sequential
//          2D rotations (12 fma-ops, 3 LDC.128 of constants per step).
//          out = r.z * w + b.
// ---------------------------------------------------------------------------
__global__ void __launch_bounds__(256) qsim_kernel(
    const float4* __restrict__ xg,
    const float* __restrict__ w,
    const float* __restrict__ b,
    float* __restrict__ out)
{
    extern __shared__ float4 s_x[];   // 512 elements * 8 float4 = 64KB

    int tid = threadIdx.x;
    size_t blockElem = (size_t)blockIdx.x * 512;
    const float4* gbase = xg + blockElem * 8;

    // Coalesced streaming load -> swizzled smem store
#pragma unroll
    for (int k = 0; k < 16; k++) {
        int idx = tid + k * 256;            // linear float4 index in block tile
        float4 v = __ldcs(gbase + idx);     // lanes consecutive: nL=4 per warp
        int e = idx >> 3;                   // local element
        int c = idx & 7;                    // chunk within window
        s_x[(e << 3) + ((c + e) & 7)] = v;  // XOR-quad swizzle
    }
    __syncthreads();

    int e0 = tid;          // lane .x element (local)
    int e1 = tid + 256;    // lane .y element (local)

    // Bloch vector of |0> for both elements
    u64 rx = pack2(0.0f, 0.0f);
    u64 ry = rx;
    u64 rz = pack2(1.0f, 1.0f);
    const u64 NEG1 = pack2(-1.0f, -1.0f);

#pragma unroll
    for (int c = 0; c < 8; c++) {
        float4 a0 = s_x[(e0 << 3) + ((c + e0) & 7)];   // LDS.128, conflict-free
        float4 a1 = s_x[(e1 << 3) + ((c + e1) & 7)];
        float xa0[4] = { a0.x, a0.y, a0.z, a0.w };
        float xa1[4] = { a1.x, a1.y, a1.z, a1.w };

#pragma unroll
        for (int j = 0; j < 4; j++) {
            int t = c * 4 + j;

            float s0, c0, s1, c1;
            __sincosf(xa0[j], &s0, &c0);               // 2x MUFU
            __sincosf(xa1[j], &s1, &c1);               // 2x MUFU

            u64 sx  = pack2(s0, s1);
            u64 cx  = pack2(c0, c1);
            u64 nsx = mul2(sx, NEG1);

            // 3x LDC.128 (compile-time offsets, uniform)
            ulonglong2 q0 = c_consts[t * 3 + 0];       // (CB, SB)
            ulonglong2 q1 = c_consts[t * 3 + 1];       // (CC, SC)
            ulonglong2 q2 = c_consts[t * 3 + 2];       // (NSB, NSC)

            // Rx(x_t): rotate (y,z); x unchanged
            u64 y1 = fma2(cx, ry, mul2(nsx, rz));      // cx*ry - sx*rz
            u64 z1 = fma2(sx, ry, mul2(cx, rz));       // sx*ry + cx*rz

            // Ry(th0): rotate (z,x)
            u64 x2 = fma2(q0.x, rx, mul2(q0.y, z1));   // cb*rx + sb*z1
            u64 z2 = fma2(q0.x, z1, mul2(q2.x, rx));   // cb*z1 - sb*rx

            // Rz(th1): rotate (x,y)
            u64 x3 = fma2(q1.x, x2, mul2(q2.y, y1));   // cc*x2 - sc*y1
            u64 y3 = fma2(q1.x, y1, mul2(q1.y, x2));   // cc*y1 + sc*x2

            rx = x3; ry = y3; rz = z2;
        }
    }

    float W  = w[0];
    float Bb = b[0];
    float z_0, z_1;
    unpack2(rz, z_0, z_1);
    out[blockElem + e0] = fmaf(z_0, W, Bb);            // coalesced stores
    out[blockElem + e1] = fmaf(z_1, W, Bb);
}

extern "C" void kernel_launch(void* const* d_in, const int* in_sizes, int n_in,
                              void* d_out, int out_size)
{
    const float* x     = (const float*)d_in[0];   // [B, 32]
    const float* theta = (const float*)d_in[1];   // [32, 2]
    const float* w     = (const float*)d_in[2];   // [1, 1]
    const float* b     = (const float*)d_in[3];   // [1]
    float* out = (float*)d_out;                   // [B]

    int B = in_sizes[0] / 32;

    prep_consts_kernel<<<1, 32>>>(theta);

    // Stage -> constant bank (device-to-device memcpy node, graph-capturable)
    void* staging_ptr = nullptr;
    cudaGetSymbolAddress(&staging_ptr, g_consts_dev);
    cudaMemcpyToSymbolAsync(c_consts, staging_ptr, sizeof(ulonglong2) * 32 * 3, 0,
                            cudaMemcpyDeviceToDevice, 0);

    const int SMEM = 512 * 8 * sizeof(float4);    // 64KB dynamic smem
    cudaFuncSetAttribute(qsim_kernel, cudaFuncAttributeMaxDynamicSharedMemorySize, SMEM);

    qsim_kernel<<<B / 512, 256, SMEM>>>((const float4*)x, w, b, out);
}